// round 10
// baseline (speedup 1.0000x reference)
#include <cuda_runtime.h>
#include <cstdint>

#define BATCH 256
#define QNUM 900
#define CNUM 91
#define QC (QNUM * CNUM)        // 81900
#define NVR (QC / 4)            // 20475 float4 per row
#define K_SEL 100
#define CAPC 1024
#define THR 2.75f
#define SEGS 8
#define SEG_F4 2560
#define T 256
#define F4PT 10
#define SBUF_CAP 512
#define PT 128                  // post threads per row

__device__ int g_cnt[BATCH];
__device__ unsigned long long g_cand[BATCH * CAPC];

__device__ __forceinline__ uint32_t mono(float f) {
    uint32_t u = __float_as_uint(f);
    return u ^ ((u >> 31) ? 0xFFFFFFFFu : 0x80000000u);
}
__device__ __forceinline__ float unmono(uint32_t m) {
    uint32_t u = (m & 0x80000000u) ? (m ^ 0x80000000u) : ~m;
    return __uint_as_float(u);
}

// ---------------- Phase 1: streaming scan (proven ~12us @ ~7TB/s) ----------------
__global__ __launch_bounds__(T)
void scan_kernel(const float* __restrict__ logits)
{
    __shared__ unsigned long long sbuf[SBUF_CAP];
    __shared__ int scnt, sbase, scopy;

    const int c = blockIdx.x;
    const int b = c >> 3;
    const int s = c & 7;
    const int tid = threadIdx.x;
    const float4* row = (const float4*)(logits + (size_t)b * QC);

    if (tid == 0) scnt = 0;
    __syncthreads();

    const int base = s * SEG_F4 + tid;
    #pragma unroll
    for (int k = 0; k < F4PT; k++) {
        int i = base + k * T;
        if (i < NVR) {
            float4 v = row[i];
            float vmax = fmaxf(fmaxf(v.x, v.y), fmaxf(v.z, v.w));
            if (vmax > THR) {
                float vl[4] = {v.x, v.y, v.z, v.w};
                #pragma unroll
                for (int l = 0; l < 4; l++) {
                    if (vl[l] > THR) {
                        int p = atomicAdd(&scnt, 1);
                        if (p < SBUF_CAP) {
                            uint32_t idx = (uint32_t)(i * 4 + l);
                            sbuf[p] = ((unsigned long long)mono(vl[l]) << 32)
                                      | (0xFFFFFFFFu - idx);
                        }
                    }
                }
            }
        }
    }
    __syncthreads();

    if (tid == 0) {
        int cnt = scnt;
        int stored = min(cnt, SBUF_CAP);
        int add = (cnt > SBUF_CAP) ? (CAPC + 1) : cnt;   // overflow -> force fallback
        sbase = atomicAdd(&g_cnt[b], add);
        scopy = stored;
    }
    __syncthreads();

    int stored = scopy, gb = sbase;
    for (int i = tid; i < stored; i += T) {
        int p = gb + i;
        if (p < CAPC) g_cand[b * CAPC + p] = sbuf[i];
    }
}

// ---------------- Phase 2: one row per CTA, 4 warps, minimal barriers ----------------
__global__ __launch_bounds__(PT)
void post_kernel(const float* __restrict__ logits,
                 const float* __restrict__ boxes_in,
                 const float* __restrict__ tsizes,
                 float* __restrict__ out)
{
    __shared__ unsigned long long skey[SBUF_CAP + 8];
    __shared__ unsigned long long stopk[K_SEL];
    __shared__ float sx0[K_SEL], sy0[K_SEL], sx1[K_SEL], sy1[K_SEL];
    __shared__ float sar[K_SEL], ssc[K_SEL];
    __shared__ uint4 ssup[K_SEL];
    __shared__ int sfcnt;
    __shared__ uint32_t skeep[4];

    const int b = blockIdx.x;
    const int tid = threadIdx.x;
    const float4* rp = (const float4*)(logits + (size_t)b * QC);

    int n = g_cnt[b];

    if (n >= K_SEL && n <= SBUF_CAP) {
        for (int i = tid; i < n; i += PT)
            skey[i] = g_cand[b * CAPC + i];
    } else {
        // ---- exact fallback: bit-descend threshold (never taken statistically) ----
        uint32_t t = 0;
        for (int bit = 31; bit >= 0; bit--) {
            uint32_t t2 = t | (1u << bit);
            int c = 0;
            for (int i = tid; i < NVR; i += PT) {
                float4 v = rp[i];
                c += (int)(mono(v.x) >= t2) + (int)(mono(v.y) >= t2)
                   + (int)(mono(v.z) >= t2) + (int)(mono(v.w) >= t2);
            }
            // block reduce via shared counter
            if (tid == 0) sfcnt = 0;
            __syncthreads();
            atomicAdd(&sfcnt, c);
            __syncthreads();
            if (sfcnt >= K_SEL) t = t2;
            __syncthreads();
        }
        if (tid == 0) sfcnt = 0;
        __syncthreads();
        for (int i = tid; i < NVR; i += PT) {
            float4 v = rp[i];
            float vl[4] = {v.x, v.y, v.z, v.w};
            #pragma unroll
            for (int l = 0; l < 4; l++) {
                uint32_t m = mono(vl[l]);
                if (m >= t) {
                    int p = atomicAdd(&sfcnt, 1);
                    if (p < SBUF_CAP) {
                        uint32_t idx = (uint32_t)(i * 4 + l);
                        skey[p] = ((unsigned long long)m << 32) | (0xFFFFFFFFu - idx);
                    }
                }
            }
        }
        __syncthreads();
        n = min(sfcnt, SBUF_CAP);
    }
    __syncthreads();
    if (tid < 8) skey[n + tid] = 0ULL;   // pad (0 < any real key)
    __syncthreads();

    // ---- rank-by-count: 2 keys per thread in regs, one unroll-4 pass ----
    {
        const int n4 = (n + 3) & ~3;
        unsigned long long k0 = (tid < n) ? skey[tid] : 0ULL;
        unsigned long long k1 = (tid + PT < n) ? skey[tid + PT] : 0ULL;
        int r0 = 0, r1 = 0;
        for (int j = 0; j < n4; j += 4) {
            unsigned long long a = skey[j + 0];
            unsigned long long b2 = skey[j + 1];
            unsigned long long c2 = skey[j + 2];
            unsigned long long d = skey[j + 3];
            r0 += (int)(a > k0) + (int)(b2 > k0) + (int)(c2 > k0) + (int)(d > k0);
            r1 += (int)(a > k1) + (int)(b2 > k1) + (int)(c2 > k1) + (int)(d > k1);
        }
        // handle n in (256, 512]: 2 more keys per thread
        if (n > 2 * PT) {
            unsigned long long k2 = (tid + 2 * PT < n) ? skey[tid + 2 * PT] : 0ULL;
            unsigned long long k3 = (tid + 3 * PT < n) ? skey[tid + 3 * PT] : 0ULL;
            int r2 = 0, r3 = 0;
            for (int j = 0; j < n4; j += 4) {
                unsigned long long a = skey[j + 0];
                unsigned long long b2 = skey[j + 1];
                unsigned long long c2 = skey[j + 2];
                unsigned long long d = skey[j + 3];
                r2 += (int)(a > k2) + (int)(b2 > k2) + (int)(c2 > k2) + (int)(d > k2);
                r3 += (int)(a > k3) + (int)(b2 > k3) + (int)(c2 > k3) + (int)(d > k3);
            }
            if (tid + 2 * PT < n && r2 < K_SEL) stopk[r2] = k2;
            if (tid + 3 * PT < n && r3 < K_SEL) stopk[r3] = k3;
        }
        if (tid < n && r0 < K_SEL) stopk[r0] = k0;
        if (tid + PT < n && r1 < K_SEL) stopk[r1] = k1;
    }
    __syncthreads();

    // ---- decode (tid < 100): prefetch, fp32 exactly as reference ----
    const int BK = BATCH * K_SEL;
    if (tid < K_SEL) {
        unsigned long long k = stopk[tid];
        uint32_t m = (uint32_t)(k >> 32);
        uint32_t idx = 0xFFFFFFFFu - (uint32_t)(k & 0xFFFFFFFFu);
        int q = idx / CNUM;
        int lab = idx - q * CNUM;
        float4 bx = __ldg((const float4*)(boxes_in + ((size_t)b * QNUM + q) * 4));
        float img_h = __ldg(&tsizes[2 * b]);
        float img_w = __ldg(&tsizes[2 * b + 1]);
        float logit = unmono(m);
        float score = 1.0f / (1.0f + expf(-logit));
        float x0 = (bx.x - 0.5f * bx.z) * img_w;
        float y0 = (bx.y - 0.5f * bx.w) * img_h;
        float x1 = (bx.x + 0.5f * bx.z) * img_w;
        float y1 = (bx.y + 0.5f * bx.w) * img_h;
        sx0[tid] = x0; sy0[tid] = y0; sx1[tid] = x1; sy1[tid] = y1;
        sar[tid] = (x1 - x0) * (y1 - y0);
        ssc[tid] = score;

        int o = b * K_SEL + tid;
        out[o] = score;
        out[BK + o] = (float)lab;
        float* ob = out + 2 * BK + (size_t)o * 4;
        ob[0] = x0; ob[1] = y0; ob[2] = x1; ob[3] = y1;
    }
    __syncthreads();

    // ---- NMS mask (tid < 100): fp32 div, same ops as reference ----
    if (tid < K_SEL) {
        float x0i = sx0[tid], y0i = sy0[tid], x1i = sx1[tid], y1i = sy1[tid];
        float ai = sar[tid];
        uint32_t mm[4] = {0, 0, 0, 0};
        #pragma unroll 4
        for (int j = tid + 1; j < K_SEL; j++) {
            float lx = fmaxf(x0i, sx0[j]);
            float ly = fmaxf(y0i, sy0[j]);
            float rx = fminf(x1i, sx1[j]);
            float ry = fminf(y1i, sy1[j]);
            float iw = fmaxf(rx - lx, 0.0f);
            float ih = fmaxf(ry - ly, 0.0f);
            float inter = iw * ih;
            float uni = ai + sar[j] - inter;
            float iou = inter / fmaxf(uni, 1e-9f);
            if (iou > 0.7f)
                mm[j >> 5] |= 1u << (j & 31);
        }
        ssup[tid] = make_uint4(mm[0], mm[1], mm[2], mm[3]);
    }
    __syncthreads();

    // ---- serial greedy chain (thread 0) ----
    if (tid == 0) {
        uint32_t k0 = ~0u, k1 = ~0u, k2 = ~0u, k3 = ~0u;
        #pragma unroll 1
        for (int i = 0; i < 32; i++) {
            if ((k0 >> i) & 1u) { uint4 s = ssup[i]; k0 &= ~s.x; k1 &= ~s.y; k2 &= ~s.z; k3 &= ~s.w; }
        }
        #pragma unroll 1
        for (int i = 32; i < 64; i++) {
            if ((k1 >> (i - 32)) & 1u) { uint4 s = ssup[i]; k0 &= ~s.x; k1 &= ~s.y; k2 &= ~s.z; k3 &= ~s.w; }
        }
        #pragma unroll 1
        for (int i = 64; i < 96; i++) {
            if ((k2 >> (i - 64)) & 1u) { uint4 s = ssup[i]; k0 &= ~s.x; k1 &= ~s.y; k2 &= ~s.z; k3 &= ~s.w; }
        }
        #pragma unroll 1
        for (int i = 96; i < K_SEL; i++) {
            if ((k3 >> (i - 96)) & 1u) { uint4 s = ssup[i]; k0 &= ~s.x; k1 &= ~s.y; k2 &= ~s.z; k3 &= ~s.w; }
        }
        skeep[0] = k0; skeep[1] = k1; skeep[2] = k2; skeep[3] = k3;
    }
    __syncthreads();

    if (tid < K_SEL) {
        int o = b * K_SEL + tid;
        bool kb = (skeep[tid >> 5] >> (tid & 31)) & 1u;
        out[6 * BK + o] = (ssc[tid] > 0.3f && kb) ? 1.0f : 0.0f;
    }

    if (tid == 0) g_cnt[b] = 0;   // reset for next replay
}

extern "C" void kernel_launch(void* const* d_in, const int* in_sizes, int n_in,
                              void* d_out, int out_size)
{
    const float* logits   = (const float*)d_in[0];   // (256, 900, 91) f32
    const float* boxes_in = (const float*)d_in[1];   // (256, 900, 4)  f32
    const float* tsizes   = (const float*)d_in[2];   // (256, 2)       f32
    float* out = (float*)d_out;
    scan_kernel<<<BATCH * SEGS, T>>>(logits);
    post_kernel<<<BATCH, PT>>>(logits, boxes_in, tsizes, out);
}

// round 11
// speedup vs baseline: 1.4325x; 1.4325x over previous
#include <cuda_runtime.h>
#include <cstdint>

#define BATCH 256
#define QNUM 900
#define CNUM 91
#define QC (QNUM * CNUM)        // 81900
#define NVR (QC / 4)            // 20475 float4 per row
#define K_SEL 100
#define CAPC 1024
#define THR 2.75f
#define SEGS 8
#define SEG_F4 2560
#define T 256
#define F4PT 10
#define SBUF_CAP 512
#define HT 128                  // threads per row-half in post

__device__ int g_cnt[BATCH];
__device__ unsigned long long g_cand[BATCH * CAPC];

__device__ __forceinline__ uint32_t mono(float f) {
    uint32_t u = __float_as_uint(f);
    return u ^ ((u >> 31) ? 0xFFFFFFFFu : 0x80000000u);
}
__device__ __forceinline__ float unmono(uint32_t m) {
    uint32_t u = (m & 0x80000000u) ? (m ^ 0x80000000u) : ~m;
    return __uint_as_float(u);
}

// ---------------- Phase 1: streaming scan (proven ~12us @ ~7TB/s) ----------------
__global__ __launch_bounds__(T)
void scan_kernel(const float* __restrict__ logits)
{
    __shared__ unsigned long long sbuf[SBUF_CAP];
    __shared__ int scnt, sbase, scopy;

    const int c = blockIdx.x;
    const int b = c >> 3;
    const int s = c & 7;
    const int tid = threadIdx.x;
    const float4* row = (const float4*)(logits + (size_t)b * QC);

    if (tid == 0) scnt = 0;
    __syncthreads();

    const int base = s * SEG_F4 + tid;
    #pragma unroll
    for (int k = 0; k < F4PT; k++) {
        int i = base + k * T;
        if (i < NVR) {
            float4 v = row[i];
            float vmax = fmaxf(fmaxf(v.x, v.y), fmaxf(v.z, v.w));
            if (vmax > THR) {
                float vl[4] = {v.x, v.y, v.z, v.w};
                #pragma unroll
                for (int l = 0; l < 4; l++) {
                    if (vl[l] > THR) {
                        int p = atomicAdd(&scnt, 1);
                        if (p < SBUF_CAP) {
                            uint32_t idx = (uint32_t)(i * 4 + l);
                            sbuf[p] = ((unsigned long long)mono(vl[l]) << 32)
                                      | (0xFFFFFFFFu - idx);
                        }
                    }
                }
            }
        }
    }
    __syncthreads();

    if (tid == 0) {
        int cnt = scnt;
        int stored = min(cnt, SBUF_CAP);
        int add = (cnt > SBUF_CAP) ? (CAPC + 1) : cnt;   // overflow -> force fallback
        sbase = atomicAdd(&g_cnt[b], add);
        scopy = stored;
    }
    __syncthreads();

    int stored = scopy, gb = sbase;
    for (int i = tid; i < stored; i += T) {
        int p = gb + i;
        if (p < CAPC) g_cand[b * CAPC + p] = sbuf[i];
    }
}

// ---------------- Phase 2: 2 rows/CTA (named-barrier halves), div-free NMS ----------------
#define BARSUB() asm volatile("bar.sync %0, %1;" :: "r"(sub + 1), "r"(HT) : "memory")

__global__ __launch_bounds__(2 * HT)
void post_kernel(const float* __restrict__ logits,
                 const float* __restrict__ boxes_in,
                 const float* __restrict__ tsizes,
                 float* __restrict__ out)
{
    __shared__ unsigned long long skey[2][SBUF_CAP + 8];
    __shared__ unsigned long long stopk[2][K_SEL];
    __shared__ float4 sbox[2][K_SEL];          // x0,y0,x1,y1
    __shared__ float sar[2][K_SEL], ssc[2][K_SEL];
    __shared__ uint4 ssup[2][K_SEL + 1];
    __shared__ int sfcnt[2];
    __shared__ uint32_t skeep[2][4];

    const int tid = threadIdx.x;
    const int sub = tid >> 7;            // 0 or 1
    const int stid = tid & (HT - 1);
    const int b = blockIdx.x * 2 + sub;
    const float4* rp = (const float4*)(logits + (size_t)b * QC);

    int n = g_cnt[b];

    if (n >= K_SEL && n <= SBUF_CAP) {
        for (int i = stid; i < n; i += HT)
            skey[sub][i] = g_cand[b * CAPC + i];
    } else {
        // ---- exact fallback: bit-descend threshold (statistically never taken) ----
        uint32_t t = 0;
        for (int bit = 31; bit >= 0; bit--) {
            uint32_t t2 = t | (1u << bit);
            int c = 0;
            for (int i = stid; i < NVR; i += HT) {
                float4 v = rp[i];
                c += (int)(mono(v.x) >= t2) + (int)(mono(v.y) >= t2)
                   + (int)(mono(v.z) >= t2) + (int)(mono(v.w) >= t2);
            }
            if (stid == 0) sfcnt[sub] = 0;
            BARSUB();
            atomicAdd(&sfcnt[sub], c);
            BARSUB();
            if (sfcnt[sub] >= K_SEL) t = t2;
            BARSUB();
        }
        if (stid == 0) sfcnt[sub] = 0;
        BARSUB();
        for (int i = stid; i < NVR; i += HT) {
            float4 v = rp[i];
            float vl[4] = {v.x, v.y, v.z, v.w};
            #pragma unroll
            for (int l = 0; l < 4; l++) {
                uint32_t m = mono(vl[l]);
                if (m >= t) {
                    int p = atomicAdd(&sfcnt[sub], 1);
                    if (p < SBUF_CAP) {
                        uint32_t idx = (uint32_t)(i * 4 + l);
                        skey[sub][p] = ((unsigned long long)m << 32) | (0xFFFFFFFFu - idx);
                    }
                }
            }
        }
        BARSUB();
        n = min(sfcnt[sub], SBUF_CAP);
    }
    BARSUB();
    if (stid < 8) skey[sub][n + stid] = 0ULL;   // pad (0 < any real key)
    BARSUB();

    // ---- rank-by-count: 4 keys/thread in regs, one unroll-4 pass (keys unique) ----
    {
        const int n4 = (n + 3) & ~3;
        unsigned long long k0 = (stid < n)          ? skey[sub][stid]          : 0ULL;
        unsigned long long k1 = (stid + HT < n)     ? skey[sub][stid + HT]     : 0ULL;
        unsigned long long k2 = (stid + 2 * HT < n) ? skey[sub][stid + 2 * HT] : 0ULL;
        unsigned long long k3 = (stid + 3 * HT < n) ? skey[sub][stid + 3 * HT] : 0ULL;
        int r0 = 0, r1 = 0, r2 = 0, r3 = 0;
        for (int j = 0; j < n4; j += 4) {
            unsigned long long a = skey[sub][j + 0];
            unsigned long long b2 = skey[sub][j + 1];
            unsigned long long c2 = skey[sub][j + 2];
            unsigned long long d = skey[sub][j + 3];
            r0 += (int)(a > k0) + (int)(b2 > k0) + (int)(c2 > k0) + (int)(d > k0);
            r1 += (int)(a > k1) + (int)(b2 > k1) + (int)(c2 > k1) + (int)(d > k1);
            r2 += (int)(a > k2) + (int)(b2 > k2) + (int)(c2 > k2) + (int)(d > k2);
            r3 += (int)(a > k3) + (int)(b2 > k3) + (int)(c2 > k3) + (int)(d > k3);
        }
        if (stid < n          && r0 < K_SEL) stopk[sub][r0] = k0;
        if (stid + HT < n     && r1 < K_SEL) stopk[sub][r1] = k1;
        if (stid + 2 * HT < n && r2 < K_SEL) stopk[sub][r2] = k2;
        if (stid + 3 * HT < n && r3 < K_SEL) stopk[sub][r3] = k3;
    }
    BARSUB();

    // ---- decode (stid < 100): fp32 exactly as reference ----
    const int BK = BATCH * K_SEL;
    if (stid < K_SEL) {
        unsigned long long k = stopk[sub][stid];
        uint32_t m = (uint32_t)(k >> 32);
        uint32_t idx = 0xFFFFFFFFu - (uint32_t)(k & 0xFFFFFFFFu);
        int q = idx / CNUM;
        int lab = idx - q * CNUM;
        float4 bx = __ldg((const float4*)(boxes_in + ((size_t)b * QNUM + q) * 4));
        float img_h = __ldg(&tsizes[2 * b]);
        float img_w = __ldg(&tsizes[2 * b + 1]);
        float logit = unmono(m);
        float score = 1.0f / (1.0f + expf(-logit));
        float x0 = (bx.x - 0.5f * bx.z) * img_w;
        float y0 = (bx.y - 0.5f * bx.w) * img_h;
        float x1 = (bx.x + 0.5f * bx.z) * img_w;
        float y1 = (bx.y + 0.5f * bx.w) * img_h;
        sbox[sub][stid] = make_float4(x0, y0, x1, y1);
        sar[sub][stid] = (x1 - x0) * (y1 - y0);
        ssc[sub][stid] = score;

        int o = b * K_SEL + stid;
        out[o] = score;
        out[BK + o] = (float)lab;
        float* ob = out + 2 * BK + (size_t)o * 4;
        ob[0] = x0; ob[1] = y0; ob[2] = x1; ob[3] = y1;
    }
    BARSUB();

    // ---- NMS mask: fixed trip, float4 LDS, guarded div-free IoU test ----
    if (stid < K_SEL) {
        float4 bi = sbox[sub][stid];
        float ai = sar[sub][stid];
        uint32_t mm[4] = {0, 0, 0, 0};
        #pragma unroll 4
        for (int j = 0; j < K_SEL; j++) {
            float4 bj = sbox[sub][j];
            float aj = sar[sub][j];
            float lx = fmaxf(bi.x, bj.x);
            float ly = fmaxf(bi.y, bj.y);
            float rx = fminf(bi.z, bj.z);
            float ry = fminf(bi.w, bj.w);
            float iw = fmaxf(rx - lx, 0.0f);
            float ih = fmaxf(ry - ly, 0.0f);
            float inter = iw * ih;
            float uni = ai + aj - inter;           // > 0 always (areas positive)
            float p = 0.7f * uni;
            float diff = inter - p;
            bool sup;
            if (fabsf(diff) > 1.2e-6f * p) {
                sup = (diff > 0.0f);               // provably equals RN(inter/uni) > 0.7f
            } else {
                sup = (inter / fmaxf(uni, 1e-9f) > 0.7f);   // exact, ~never taken
            }
            if (sup && j > stid)
                mm[j >> 5] |= 1u << (j & 31);
        }
        ssup[sub][stid] = make_uint4(mm[0], mm[1], mm[2], mm[3]);
    }
    if (stid == 0) ssup[sub][K_SEL] = make_uint4(0, 0, 0, 0);
    BARSUB();

    // ---- serial greedy chain (prefetched; hidden by sibling half) ----
    if (stid == 0) {
        uint32_t k0 = ~0u, k1 = ~0u, k2 = ~0u, k3 = ~0u;
        uint4 sv = ssup[sub][0];
        #pragma unroll 1
        for (int i = 0; i < 32; i++) {
            uint4 sn = ssup[sub][i + 1];
            if ((k0 >> i) & 1u) { k0 &= ~sv.x; k1 &= ~sv.y; k2 &= ~sv.z; k3 &= ~sv.w; }
            sv = sn;
        }
        #pragma unroll 1
        for (int i = 32; i < 64; i++) {
            uint4 sn = ssup[sub][i + 1];
            if ((k1 >> (i - 32)) & 1u) { k0 &= ~sv.x; k1 &= ~sv.y; k2 &= ~sv.z; k3 &= ~sv.w; }
            sv = sn;
        }
        #pragma unroll 1
        for (int i = 64; i < 96; i++) {
            uint4 sn = ssup[sub][i + 1];
            if ((k2 >> (i - 64)) & 1u) { k0 &= ~sv.x; k1 &= ~sv.y; k2 &= ~sv.z; k3 &= ~sv.w; }
            sv = sn;
        }
        #pragma unroll 1
        for (int i = 96; i < K_SEL; i++) {
            uint4 sn = ssup[sub][i + 1];
            if ((k3 >> (i - 96)) & 1u) { k0 &= ~sv.x; k1 &= ~sv.y; k2 &= ~sv.z; k3 &= ~sv.w; }
            sv = sn;
        }
        skeep[sub][0] = k0; skeep[sub][1] = k1; skeep[sub][2] = k2; skeep[sub][3] = k3;
    }
    BARSUB();

    if (stid < K_SEL) {
        int o = b * K_SEL + stid;
        bool kb = (skeep[sub][stid >> 5] >> (stid & 31)) & 1u;
        out[6 * BK + o] = (ssc[sub][stid] > 0.3f && kb) ? 1.0f : 0.0f;
    }

    if (stid == 0) g_cnt[b] = 0;   // reset for next replay
}

extern "C" void kernel_launch(void* const* d_in, const int* in_sizes, int n_in,
                              void* d_out, int out_size)
{
    const float* logits   = (const float*)d_in[0];   // (256, 900, 91) f32
    const float* boxes_in = (const float*)d_in[1];   // (256, 900, 4)  f32
    const float* tsizes   = (const float*)d_in[2];   // (256, 2)       f32
    float* out = (float*)d_out;
    scan_kernel<<<BATCH * SEGS, T>>>(logits);
    post_kernel<<<BATCH / 2, 2 * HT>>>(logits, boxes_in, tsizes, out);
}

// round 12
// speedup vs baseline: 1.4338x; 1.0009x over previous
#include <cuda_runtime.h>
#include <cstdint>

#define BATCH 256
#define QNUM 900
#define CNUM 91
#define QC (QNUM * CNUM)        // 81900
#define NVR (QC / 4)            // 20475 float4 per row
#define K_SEL 100
#define CAPC 1024
#define THR 2.85f
#define SEGS 8
#define SEG_F4 2560
#define T 256
#define F4PT 10
#define SBUF_CAP 512
#define HT 128                  // threads per row-half in post

__device__ int g_cnt[BATCH];
__device__ unsigned long long g_cand[BATCH * CAPC];

__device__ __forceinline__ uint32_t mono(float f) {
    uint32_t u = __float_as_uint(f);
    return u ^ ((u >> 31) ? 0xFFFFFFFFu : 0x80000000u);
}
__device__ __forceinline__ float unmono(uint32_t m) {
    uint32_t u = (m & 0x80000000u) ? (m ^ 0x80000000u) : ~m;
    return __uint_as_float(u);
}

// ---------------- Phase 1: streaming scan (proven ~11-12us @ ~7TB/s) ----------------
__global__ __launch_bounds__(T)
void scan_kernel(const float* __restrict__ logits)
{
    __shared__ unsigned long long sbuf[SBUF_CAP];
    __shared__ int scnt, sbase, scopy;

    const int c = blockIdx.x;
    const int b = c >> 3;
    const int s = c & 7;
    const int tid = threadIdx.x;
    const float4* row = (const float4*)(logits + (size_t)b * QC);

    if (tid == 0) scnt = 0;
    __syncthreads();

    const int base = s * SEG_F4 + tid;
    #pragma unroll
    for (int k = 0; k < F4PT; k++) {
        int i = base + k * T;
        if (i < NVR) {
            float4 v = row[i];
            float vmax = fmaxf(fmaxf(v.x, v.y), fmaxf(v.z, v.w));
            if (vmax > THR) {
                float vl[4] = {v.x, v.y, v.z, v.w};
                #pragma unroll
                for (int l = 0; l < 4; l++) {
                    if (vl[l] > THR) {
                        int p = atomicAdd(&scnt, 1);
                        if (p < SBUF_CAP) {
                            uint32_t idx = (uint32_t)(i * 4 + l);
                            sbuf[p] = ((unsigned long long)mono(vl[l]) << 32)
                                      | (0xFFFFFFFFu - idx);
                        }
                    }
                }
            }
        }
    }
    __syncthreads();

    if (tid == 0) {
        int cnt = scnt;
        int stored = min(cnt, SBUF_CAP);
        int add = (cnt > SBUF_CAP) ? (CAPC + 1) : cnt;   // overflow -> force fallback
        sbase = atomicAdd(&g_cnt[b], add);
        scopy = stored;
    }
    __syncthreads();

    int stored = scopy, gb = sbase;
    for (int i = tid; i < stored; i += T) {
        int p = gb + i;
        if (p < CAPC) g_cand[b * CAPC + p] = sbuf[i];
    }
}

// ---------------- Phase 2: 2 rows/CTA, rank-fused decode, triangular NMS ----------------
#define BARSUB() asm volatile("bar.sync %0, %1;" :: "r"(sub + 1), "r"(HT) : "memory")

__global__ __launch_bounds__(2 * HT)
void post_kernel(const float* __restrict__ logits,
                 const float* __restrict__ boxes_in,
                 const float* __restrict__ tsizes,
                 float* __restrict__ out)
{
    __shared__ unsigned long long skey[2][SBUF_CAP + 8];
    __shared__ float4 sbox[2][K_SEL];          // x0,y0,x1,y1 at rank position
    __shared__ float sar[2][K_SEL], ssc[2][K_SEL];
    __shared__ uint4 ssup[2][K_SEL + 1];
    __shared__ int sfcnt[2];
    __shared__ uint32_t skeep[2][4];

    const int tid = threadIdx.x;
    const int sub = tid >> 7;            // 0 or 1
    const int stid = tid & (HT - 1);
    const int b = blockIdx.x * 2 + sub;
    const float4* rp = (const float4*)(logits + (size_t)b * QC);
    const int BK = BATCH * K_SEL;

    int n = g_cnt[b];

    if (n >= K_SEL && n <= SBUF_CAP) {
        for (int i = stid; i < n; i += HT)
            skey[sub][i] = g_cand[b * CAPC + i];
    } else {
        // ---- exact fallback: bit-descend threshold (statistically never taken) ----
        uint32_t t = 0;
        for (int bit = 31; bit >= 0; bit--) {
            uint32_t t2 = t | (1u << bit);
            int c = 0;
            for (int i = stid; i < NVR; i += HT) {
                float4 v = rp[i];
                c += (int)(mono(v.x) >= t2) + (int)(mono(v.y) >= t2)
                   + (int)(mono(v.z) >= t2) + (int)(mono(v.w) >= t2);
            }
            if (stid == 0) sfcnt[sub] = 0;
            BARSUB();
            atomicAdd(&sfcnt[sub], c);
            BARSUB();
            if (sfcnt[sub] >= K_SEL) t = t2;
            BARSUB();
        }
        if (stid == 0) sfcnt[sub] = 0;
        BARSUB();
        for (int i = stid; i < NVR; i += HT) {
            float4 v = rp[i];
            float vl[4] = {v.x, v.y, v.z, v.w};
            #pragma unroll
            for (int l = 0; l < 4; l++) {
                uint32_t m = mono(vl[l]);
                if (m >= t) {
                    int p = atomicAdd(&sfcnt[sub], 1);
                    if (p < SBUF_CAP) {
                        uint32_t idx = (uint32_t)(i * 4 + l);
                        skey[sub][p] = ((unsigned long long)m << 32) | (0xFFFFFFFFu - idx);
                    }
                }
            }
        }
        BARSUB();
        n = min(sfcnt[sub], SBUF_CAP);
    }
    BARSUB();
    if (stid < 8) skey[sub][n + stid] = 0ULL;   // pad (0 < any real key)
    BARSUB();

    // ---- rank-by-count (4 keys/thread, unroll-4) with FUSED decode ----
    {
        const int n4 = (n + 3) & ~3;
        unsigned long long kk[4];
        int rr[4];
        #pragma unroll
        for (int r = 0; r < 4; r++) {
            int slot = stid + r * HT;
            kk[r] = (slot < n) ? skey[sub][slot] : 0ULL;
            rr[r] = 0;
        }
        for (int j = 0; j < n4; j += 4) {
            unsigned long long a = skey[sub][j + 0];
            unsigned long long b2 = skey[sub][j + 1];
            unsigned long long c2 = skey[sub][j + 2];
            unsigned long long d = skey[sub][j + 3];
            #pragma unroll
            for (int r = 0; r < 4; r++)
                rr[r] += (int)(a > kk[r]) + (int)(b2 > kk[r])
                       + (int)(c2 > kk[r]) + (int)(d > kk[r]);
        }
        // inline decode: thread holding a top-100 key writes it at its rank
        const float img_h = __ldg(&tsizes[2 * b]);
        const float img_w = __ldg(&tsizes[2 * b + 1]);
        #pragma unroll
        for (int r = 0; r < 4; r++) {
            int slot = stid + r * HT;
            if (slot < n && rr[r] < K_SEL) {
                int rank = rr[r];
                uint32_t m = (uint32_t)(kk[r] >> 32);
                uint32_t idx = 0xFFFFFFFFu - (uint32_t)(kk[r] & 0xFFFFFFFFu);
                int q = idx / CNUM;
                int lab = idx - q * CNUM;
                float4 bx = __ldg((const float4*)(boxes_in + ((size_t)b * QNUM + q) * 4));
                float logit = unmono(m);
                float score = 1.0f / (1.0f + expf(-logit));
                float x0 = (bx.x - 0.5f * bx.z) * img_w;
                float y0 = (bx.y - 0.5f * bx.w) * img_h;
                float x1 = (bx.x + 0.5f * bx.z) * img_w;
                float y1 = (bx.y + 0.5f * bx.w) * img_h;
                sbox[sub][rank] = make_float4(x0, y0, x1, y1);
                sar[sub][rank] = (x1 - x0) * (y1 - y0);
                ssc[sub][rank] = score;

                int o = b * K_SEL + rank;
                out[o] = score;
                out[BK + o] = (float)lab;
                float* ob = out + 2 * BK + (size_t)o * 4;
                ob[0] = x0; ob[1] = y0; ob[2] = x1; ob[3] = y1;
            }
        }
    }
    BARSUB();

    // ---- NMS mask: triangular (j > i), guarded div-free IoU test ----
    if (stid < K_SEL) {
        float4 bi = sbox[sub][stid];
        float ai = sar[sub][stid];
        uint32_t mm[4] = {0, 0, 0, 0};
        #pragma unroll 4
        for (int j = stid + 1; j < K_SEL; j++) {
            float4 bj = sbox[sub][j];
            float aj = sar[sub][j];
            float lx = fmaxf(bi.x, bj.x);
            float ly = fmaxf(bi.y, bj.y);
            float rx = fminf(bi.z, bj.z);
            float ry = fminf(bi.w, bj.w);
            float iw = fmaxf(rx - lx, 0.0f);
            float ih = fmaxf(ry - ly, 0.0f);
            float inter = iw * ih;
            float uni = ai + aj - inter;           // > 0 (areas positive)
            float p = 0.7f * uni;
            float diff = inter - p;
            bool sup;
            if (fabsf(diff) > 1.2e-6f * p) {
                sup = (diff > 0.0f);               // equals RN(inter/uni) > 0.7f
            } else {
                sup = (inter / fmaxf(uni, 1e-9f) > 0.7f);   // exact, ~never taken
            }
            if (sup)
                mm[j >> 5] |= 1u << (j & 31);
        }
        ssup[sub][stid] = make_uint4(mm[0], mm[1], mm[2], mm[3]);
    }
    if (stid == 0) ssup[sub][K_SEL] = make_uint4(0, 0, 0, 0);
    BARSUB();

    // ---- serial greedy chain (prefetched; hidden by sibling half) ----
    if (stid == 0) {
        uint32_t k0 = ~0u, k1 = ~0u, k2 = ~0u, k3 = ~0u;
        uint4 sv = ssup[sub][0];
        #pragma unroll 1
        for (int i = 0; i < 32; i++) {
            uint4 sn = ssup[sub][i + 1];
            if ((k0 >> i) & 1u) { k0 &= ~sv.x; k1 &= ~sv.y; k2 &= ~sv.z; k3 &= ~sv.w; }
            sv = sn;
        }
        #pragma unroll 1
        for (int i = 32; i < 64; i++) {
            uint4 sn = ssup[sub][i + 1];
            if ((k1 >> (i - 32)) & 1u) { k0 &= ~sv.x; k1 &= ~sv.y; k2 &= ~sv.z; k3 &= ~sv.w; }
            sv = sn;
        }
        #pragma unroll 1
        for (int i = 64; i < 96; i++) {
            uint4 sn = ssup[sub][i + 1];
            if ((k2 >> (i - 64)) & 1u) { k0 &= ~sv.x; k1 &= ~sv.y; k2 &= ~sv.z; k3 &= ~sv.w; }
            sv = sn;
        }
        #pragma unroll 1
        for (int i = 96; i < K_SEL; i++) {
            uint4 sn = ssup[sub][i + 1];
            if ((k3 >> (i - 96)) & 1u) { k0 &= ~sv.x; k1 &= ~sv.y; k2 &= ~sv.z; k3 &= ~sv.w; }
            sv = sn;
        }
        skeep[sub][0] = k0; skeep[sub][1] = k1; skeep[sub][2] = k2; skeep[sub][3] = k3;
    }
    BARSUB();

    if (stid < K_SEL) {
        int o = b * K_SEL + stid;
        bool kb = (skeep[sub][stid >> 5] >> (stid & 31)) & 1u;
        out[6 * BK + o] = (ssc[sub][stid] > 0.3f && kb) ? 1.0f : 0.0f;
    }

    if (stid == 0) g_cnt[b] = 0;   // reset for next replay
}

extern "C" void kernel_launch(void* const* d_in, const int* in_sizes, int n_in,
                              void* d_out, int out_size)
{
    const float* logits   = (const float*)d_in[0];   // (256, 900, 91) f32
    const float* boxes_in = (const float*)d_in[1];   // (256, 900, 4)  f32
    const float* tsizes   = (const float*)d_in[2];   // (256, 2)       f32
    float* out = (float*)d_out;
    scan_kernel<<<BATCH * SEGS, T>>>(logits);
    post_kernel<<<BATCH / 2, 2 * HT>>>(logits, boxes_in, tsizes, out);
}